// round 2
// baseline (speedup 1.0000x reference)
#include <cuda_runtime.h>
#include <math.h>
#include <stdint.h>

#define B_ROWS 1024
#define M_TOT  200000
#define D_INP  256
#define DIM    128
#define D_OUT  10
#define TILE_M 128
#define NTILES ((M_TOT + TILE_M - 1) / TILE_M)   /* 1563 */
#define M_PAD  (NTILES * TILE_M)                 /* 200064 */
#define MAX_CTAS 512

// ---------------- device scratch (static globals: no runtime allocation) ----
__device__ float g_hT  [DIM * B_ROWS];     // h transposed: [d][b]
__device__ float g_hn2 [B_ROWS];
__device__ float g_hcT [DIM * M_PAD];      // hc transposed: [d][m], padded
__device__ float g_hcn2[M_PAD];
__device__ float g_part[(size_t)MAX_CTAS * B_ROWS * D_OUT];

// ---------------- kernel 1: h = x @ W^T + b, hn2 ----------------------------
__global__ void k_h(const float* __restrict__ x, const float* __restrict__ W,
                    const float* __restrict__ be) {
    __shared__ float xs[D_INP];
    __shared__ float red[DIM];
    int b = blockIdx.x, t = threadIdx.x;          // 128 threads
    xs[t]       = x[(size_t)b * D_INP + t];
    xs[t + 128] = x[(size_t)b * D_INP + t + 128];
    __syncthreads();
    const float4* W4 = (const float4*)(W + (size_t)t * D_INP);
    float s = be[t];
#pragma unroll 8
    for (int k4 = 0; k4 < D_INP / 4; k4++) {
        float4 w = W4[k4];
        s += w.x * xs[k4 * 4 + 0] + w.y * xs[k4 * 4 + 1]
           + w.z * xs[k4 * 4 + 2] + w.w * xs[k4 * 4 + 3];
    }
    g_hT[(size_t)t * B_ROWS + b] = s;
    red[t] = s * s;
    __syncthreads();
    for (int off = 64; off > 0; off >>= 1) {
        if (t < off) red[t] += red[t + off];
        __syncthreads();
    }
    if (t == 0) g_hn2[b] = red[0];
}

// ---------------- kernel 2: hc = candidate_x @ W^T + b (tiled SGEMM) --------
// tile: 128 rows (m) x 128 cols (d), K = 256 in chunks of 32.
__global__ __launch_bounds__(256) void k_hc(const float* __restrict__ cx,
                                            const float* __restrict__ W,
                                            const float* __restrict__ be) {
    __shared__ float cxs[32 * 132];   // [k][m] transposed staging
    __shared__ float ws [32 * 132];   // [k][d] transposed staging
    int tile = blockIdx.x;
    int tid  = threadIdx.x;
    int tx = tid & 15;   // m group
    int ty = tid >> 4;   // d group
    float acc[8][8];
#pragma unroll
    for (int i = 0; i < 8; i++)
#pragma unroll
        for (int j = 0; j < 8; j++) acc[i][j] = 0.f;

    int m_base = tile * TILE_M;
    for (int k0 = 0; k0 < D_INP; k0 += 32) {
#pragma unroll
        for (int i = 0; i < 4; i++) {
            int idx = tid + i * 256;   // 0..1023
            int r   = idx >> 3;        // row index (m for cx, d for W), 0..127
            int kq  = idx & 7;         // which float4 along k-chunk
            int mg  = m_base + r;
            float4 v = make_float4(0.f, 0.f, 0.f, 0.f);
            if (mg < M_TOT)
                v = *(const float4*)(cx + (size_t)mg * D_INP + k0 + kq * 4);
            cxs[(kq * 4 + 0) * 132 + r] = v.x;
            cxs[(kq * 4 + 1) * 132 + r] = v.y;
            cxs[(kq * 4 + 2) * 132 + r] = v.z;
            cxs[(kq * 4 + 3) * 132 + r] = v.w;
            float4 w = *(const float4*)(W + (size_t)r * D_INP + k0 + kq * 4);
            ws [(kq * 4 + 0) * 132 + r] = w.x;
            ws [(kq * 4 + 1) * 132 + r] = w.y;
            ws [(kq * 4 + 2) * 132 + r] = w.z;
            ws [(kq * 4 + 3) * 132 + r] = w.w;
        }
        __syncthreads();
#pragma unroll 4
        for (int k = 0; k < 32; k++) {
            float4 a0 = *(const float4*)(cxs + k * 132 + tx * 4);
            float4 a1 = *(const float4*)(cxs + k * 132 + tx * 4 + 64);
            float4 b0 = *(const float4*)(ws  + k * 132 + ty * 4);
            float4 b1 = *(const float4*)(ws  + k * 132 + ty * 4 + 64);
            float av[8] = {a0.x, a0.y, a0.z, a0.w, a1.x, a1.y, a1.z, a1.w};
            float bv[8] = {b0.x, b0.y, b0.z, b0.w, b1.x, b1.y, b1.z, b1.w};
#pragma unroll
            for (int i = 0; i < 8; i++)
#pragma unroll
                for (int j = 0; j < 8; j++) acc[i][j] += av[i] * bv[j];
        }
        __syncthreads();
    }

    // epilogue: add bias, write g_hcT [d][m], compute hcn2
    float bias[8];
#pragma unroll
    for (int j = 0; j < 8; j++) bias[j] = be[ty * 4 + (j & 3) + (j >> 2) * 64];
    float psum[8];
#pragma unroll
    for (int i = 0; i < 8; i++) psum[i] = 0.f;
#pragma unroll
    for (int i = 0; i < 8; i++) {
        int m = m_base + tx * 4 + (i & 3) + (i >> 2) * 64;
#pragma unroll
        for (int j = 0; j < 8; j++) {
            int d = ty * 4 + (j & 3) + (j >> 2) * 64;
            float v = acc[i][j] + bias[j];
            psum[i] += v * v;
            g_hcT[(size_t)d * M_PAD + m] = v;
        }
    }
    __syncthreads();                  // reuse cxs as [16][128] reduce buffer
    float* red = cxs;
#pragma unroll
    for (int i = 0; i < 8; i++) {
        int mloc = tx * 4 + (i & 3) + (i >> 2) * 64;
        red[ty * 128 + mloc] = psum[i];
    }
    __syncthreads();
    if (tid < 128) {
        float s = 0.f;
        for (int g = 0; g < 16; g++) s += red[g * 128 + tid];
        g_hcn2[m_base + tid] = s;
    }
}

// ---------------- kernel 3: fused dist-GEMM + exp + class accumulation ------
#define SMEM_MAIN_BYTES ((128*128 + 128*128 + 64*132 + 1024*10 + 128 + 128) * 4 + 128)

__global__ __launch_bounds__(256) void k_main(const int* __restrict__ cy) {
    extern __shared__ char smem[];
    float* h_s    = (float*)smem;              // 128k x 128b  (64 KB)
    float* hc_s   = h_s   + 128 * 128;         // 128k x 128m  (64 KB)
    float* e_s    = hc_s  + 128 * 128;         // 64 x 132     (33 KB, reused as ls)
    float* s_s    = e_s   + 64 * 132;          // 1024 x 10    (40 KB)
    float* hn2_s  = s_s   + 1024 * 10;         // 128
    float* hcn2_s = hn2_s + 128;               // 128
    unsigned char* cls_s = (unsigned char*)(hcn2_s + 128);   // 128 bytes

    int tid = threadIdx.x;
    int tm = tid & 15, tb = tid >> 4;

    for (int i = tid; i < 1024 * 10; i += 256) s_s[i] = 0.f;

    const float4* hcT4 = (const float4*)g_hcT;   // [128][M_PAD/4]
    const float4* hT4  = (const float4*)g_hT;    // [128][256]
    float4* h4 = (float4*)h_s;
    float4* c4 = (float4*)hc_s;

    for (int tile = blockIdx.x; tile < NTILES; tile += gridDim.x) {
        __syncthreads();   // protect hc_s / cls_s reuse across tiles
#pragma unroll
        for (int i = 0; i < 16; i++) {
            int idx = tid + i * 256;             // 4096 float4
            int d = idx >> 5, m4 = idx & 31;
            c4[d * 32 + m4] = hcT4[(size_t)d * (M_PAD / 4) + tile * 32 + m4];
        }
        if (tid < 128) {
            int mg = tile * TILE_M + tid;
            hcn2_s[tid] = g_hcn2[mg];
            cls_s[tid] = (mg < M_TOT) ? (unsigned char)cy[mg] : (unsigned char)255;
        }
        __syncthreads();

        for (int ch = 0; ch < 8; ch++) {
#pragma unroll
            for (int i = 0; i < 16; i++) {
                int idx = tid + i * 256;
                int d = idx >> 5, b4 = idx & 31;
                h4[d * 32 + b4] = hT4[(size_t)d * (B_ROWS / 4) + ch * 32 + b4];
            }
            if (tid < 128) hn2_s[tid] = g_hn2[ch * 128 + tid];
            __syncthreads();

            float acc[8][8];
#pragma unroll
            for (int i = 0; i < 8; i++)
#pragma unroll
                for (int j = 0; j < 8; j++) acc[i][j] = 0.f;

#pragma unroll 4
            for (int k = 0; k < 128; k++) {
                float4 a0 = h4[k * 32 + tb], a1 = h4[k * 32 + tb + 16];
                float4 b0 = c4[k * 32 + tm], b1 = c4[k * 32 + tm + 16];
                float av[8] = {a0.x, a0.y, a0.z, a0.w, a1.x, a1.y, a1.z, a1.w};
                float bv[8] = {b0.x, b0.y, b0.z, b0.w, b1.x, b1.y, b1.z, b1.w};
#pragma unroll
                for (int i = 0; i < 8; i++)
#pragma unroll
                    for (int j = 0; j < 8; j++) acc[i][j] += av[i] * bv[j];
            }

            // dist + exp (overwrite acc with e)
            float hn[8], cn[8];
#pragma unroll
            for (int i = 0; i < 8; i++) hn[i] = hn2_s[tb * 4 + (i & 3) + (i >> 2) * 64];
#pragma unroll
            for (int j = 0; j < 8; j++) cn[j] = hcn2_s[tm * 4 + (j & 3) + (j >> 2) * 64];
#pragma unroll
            for (int i = 0; i < 8; i++)
#pragma unroll
                for (int j = 0; j < 8; j++) {
                    float sq = fmaxf(hn[i] + cn[j] - 2.f * acc[i][j], 0.f);
                    acc[i][j] = __expf(-sqrtf(sq));
                }

#pragma unroll 1
            for (int half = 0; half < 2; half++) {
                __syncthreads();
#pragma unroll
                for (int i2 = 0; i2 < 4; i2++) {
                    int i = half * 4 + i2;
                    int r = tb * 4 + i2;          // local row 0..63
                    *(float4*)(e_s + r * 132 + tm * 4) =
                        make_float4(acc[i][0], acc[i][1], acc[i][2], acc[i][3]);
                    *(float4*)(e_s + r * 132 + tm * 4 + 64) =
                        make_float4(acc[i][4], acc[i][5], acc[i][6], acc[i][7]);
                }
                __syncthreads();
                // class-bucketed accumulation: 4 threads per row, 32 m each
                int bl = tid >> 2, q = tid & 3;
                float l[10];
#pragma unroll
                for (int c = 0; c < 10; c++) l[c] = 0.f;
#pragma unroll
                for (int t8 = 0; t8 < 8; t8++) {
                    float4 ev = *(const float4*)(e_s + bl * 132 + q * 32 + t8 * 4);
                    uchar4 cvv = *(const uchar4*)(cls_s + q * 32 + t8 * 4);
#pragma unroll
                    for (int c = 0; c < 10; c++) {
                        l[c] += (cvv.x == c) ? ev.x : 0.f;
                        l[c] += (cvv.y == c) ? ev.y : 0.f;
                        l[c] += (cvv.z == c) ? ev.z : 0.f;
                        l[c] += (cvv.w == c) ? ev.w : 0.f;
                    }
                }
                __syncthreads();
                float* ls = e_s;                  // reuse e_s as [256][10]
#pragma unroll
                for (int c = 0; c < 10; c++) ls[tid * 10 + c] = l[c];
                __syncthreads();
                for (int cell = tid; cell < 640; cell += 256) {
                    int bb = cell / 10, c = cell - bb * 10;
                    float v = ls[(bb * 4 + 0) * 10 + c] + ls[(bb * 4 + 1) * 10 + c]
                            + ls[(bb * 4 + 2) * 10 + c] + ls[(bb * 4 + 3) * 10 + c];
                    s_s[(ch * 128 + half * 64 + bb) * 10 + c] += v;
                }
            }
            __syncthreads();
        }
    }
    __syncthreads();
    for (int i = tid; i < 1024 * 10; i += 256)
        g_part[(size_t)blockIdx.x * (B_ROWS * D_OUT) + i] = s_s[i];
}

// ---------------- kernel 4: merge partials, softmax normalize, log ----------
__global__ void k_final(float* __restrict__ out, int nctas) {
    int b = blockIdx.x, t = threadIdx.x;   // 32 threads
    __shared__ float sc[10];
    if (t < 10) {
        float s = 0.f;
        for (int p = 0; p < nctas; p++)
            s += g_part[(size_t)p * (B_ROWS * D_OUT) + b * 10 + t];
        sc[t] = s;
    }
    __syncthreads();
    if (t < 10) {
        float tot = 0.f;
#pragma unroll
        for (int c = 0; c < 10; c++) tot += sc[c];
        out[b * 10 + t] = logf(sc[t] / tot + 1e-7f);
    }
}

// ---------------- launch -----------------------------------------------------
extern "C" void kernel_launch(void* const* d_in, const int* in_sizes, int n_in,
                              void* d_out, int out_size) {
    const float* x  = (const float*)d_in[0];
    const float* cx = (const float*)d_in[2];
    const int*   cy = (const int*)d_in[3];
    const float* W  = (const float*)d_in[4];
    const float* be = (const float*)d_in[5];
    float* out = (float*)d_out;

    int dev = 0;
    cudaGetDevice(&dev);
    int nsm = 148;
    cudaDeviceGetAttribute(&nsm, cudaDevAttrMultiProcessorCount, dev);
    int nctas = nsm;
    if (nctas > MAX_CTAS) nctas = MAX_CTAS;
    if (nctas < 1) nctas = 148;

    cudaFuncSetAttribute(k_main, cudaFuncAttributeMaxDynamicSharedMemorySize,
                         SMEM_MAIN_BYTES);

    k_h<<<B_ROWS, 128>>>(x, W, be);
    k_hc<<<NTILES, 256>>>(cx, W, be);
    k_main<<<nctas, 256, SMEM_MAIN_BYTES>>>(cy);
    k_final<<<B_ROWS, 32>>>(out, nctas);
}

// round 4
// speedup vs baseline: 5.5440x; 5.5440x over previous
#include <cuda_runtime.h>
#include <cuda_fp16.h>
#include <math.h>
#include <stdint.h>

#define B_ROWS 1024
#define M_TOT  200000
#define D_INP  256
#define DIM    128
#define D_OUT  10
#define M_PAD  200192            /* 1564*128 */
#define N_MT   1564              /* m-tiles of 128 */
#define NBLK   782               /* histogram blocks of 256 */
#define MAX_CTAS 512

// ---------------------------------------------------------------- helpers
__device__ __forceinline__ uint32_t smem_to_u32(const void* p) {
    uint32_t a;
    asm("{ .reg .u64 t; cvta.to.shared.u64 t, %1; cvt.u32.u64 %0, t; }"
        : "=r"(a) : "l"(p));
    return a;
}
__device__ __forceinline__ void ldsm4(uint32_t r[4], uint32_t addr) {
    asm volatile("ldmatrix.sync.aligned.m8n8.x4.shared.b16 {%0,%1,%2,%3}, [%4];"
                 : "=r"(r[0]), "=r"(r[1]), "=r"(r[2]), "=r"(r[3]) : "r"(addr));
}
__device__ __forceinline__ void mma16816(float c[4], const uint32_t a[4],
                                         const uint32_t b0, const uint32_t b1) {
    asm volatile("mma.sync.aligned.m16n8k16.row.col.f32.f16.f16.f32 "
                 "{%0,%1,%2,%3}, {%4,%5,%6,%7}, {%8,%9}, {%0,%1,%2,%3};"
                 : "+f"(c[0]), "+f"(c[1]), "+f"(c[2]), "+f"(c[3])
                 : "r"(a[0]), "r"(a[1]), "r"(a[2]), "r"(a[3]), "r"(b0), "r"(b1));
}
// A-fragment ldmatrix (16 rows x 16 k), K-contiguous rows, XOR-swizzled
__device__ __forceinline__ void lda_frag(uint32_t a[4], uint32_t base, int R0,
                                         int ks, int lane, int rstride) {
    int row = R0 + (lane & 15);
    int kb  = ks * 32 + ((lane >> 4) << 4);
    ldsm4(a, base + row * rstride + (kb ^ ((row & 7) << 4)));
}
// B-fragment ldmatrix: two n-tiles of 8 (rows = n, k-contiguous)
__device__ __forceinline__ void ldb_frag(uint32_t b[4], uint32_t base, int N0,
                                         int ks, int lane, int rstride) {
    int row = N0 + (lane & 7) + ((lane >> 4) << 3);
    int kb  = ks * 32 + ((lane >> 3) & 1) * 16;
    ldsm4(b, base + row * rstride + (kb ^ ((row & 7) << 4)));
}

// ---------------------------------------------------------------- scratch
__device__ __half g_h   [B_ROWS * DIM];
__device__ float  g_hn2 [B_ROWS];
__device__ __half g_hc  [(size_t)M_PAD * DIM];
__device__ float  g_hcn2[M_PAD];
__device__ int    g_src [M_PAD];
__device__ int    g_cls [M_PAD];
__device__ int    g_bh  [NBLK * D_OUT];
__device__ int    g_boff[NBLK * D_OUT];
__device__ int    g_coff[D_OUT];
__device__ float  g_part[(size_t)MAX_CTAS * B_ROWS * D_OUT];

// ---------------------------------------------------------------- sort
__global__ void k_hist(const int* __restrict__ cy) {
    __shared__ int cnt[D_OUT];
    int t = threadIdx.x, b = blockIdx.x;
    if (t < D_OUT) cnt[t] = 0;
    __syncthreads();
    int m = b * 256 + t;
    if (m < M_TOT) atomicAdd(&cnt[cy[m]], 1);
    __syncthreads();
    if (t < D_OUT) g_bh[b * D_OUT + t] = cnt[t];
}
__global__ void k_scan() {
    __shared__ int tot[D_OUT];
    int t = threadIdx.x;
    if (t < D_OUT) {
        int run = 0;
        for (int b = 0; b < NBLK; b++) {
            int v = g_bh[b * D_OUT + t];
            g_boff[b * D_OUT + t] = run;
            run += v;
        }
        tot[t] = run;
    }
    __syncthreads();
    if (t == 0) {
        int off = 0;
        for (int c = 0; c < D_OUT; c++) { g_coff[c] = off; off += tot[c]; }
        for (int p = M_TOT; p < M_PAD; p++) g_cls[p] = D_OUT - 1;
    }
}
__global__ void k_rank(const int* __restrict__ cy) {
    __shared__ int cls[256];
    int t = threadIdx.x, b = blockIdx.x;
    int m = b * 256 + t;
    int c = (m < M_TOT) ? cy[m] : -1;
    cls[t] = c;
    __syncthreads();
    if (m < M_TOT) {
        int r = 0;
        for (int j = 0; j < t; j++) r += (cls[j] == c);
        int pos = g_coff[c] + g_boff[b * D_OUT + c] + r;
        g_src[pos] = m;
        g_cls[pos] = c;
    }
}

// ---------------------------------------------------------------- k_h
__global__ void k_h(const float* __restrict__ x, const float* __restrict__ W,
                    const float* __restrict__ be) {
    __shared__ float xs[D_INP];
    __shared__ float red[DIM];
    int b = blockIdx.x, t = threadIdx.x;      // 128 threads
    xs[t]       = x[(size_t)b * D_INP + t];
    xs[t + 128] = x[(size_t)b * D_INP + t + 128];
    __syncthreads();
    const float4* W4 = (const float4*)(W + (size_t)t * D_INP);
    float s = be[t];
#pragma unroll 8
    for (int k4 = 0; k4 < D_INP / 4; k4++) {
        float4 w = W4[k4];
        s += w.x * xs[k4*4+0] + w.y * xs[k4*4+1] + w.z * xs[k4*4+2] + w.w * xs[k4*4+3];
    }
    __half hh = __float2half_rn(s);
    g_h[b * DIM + t] = hh;
    float sr = __half2float(hh);
    red[t] = sr * sr;
    __syncthreads();
    for (int off = 64; off > 0; off >>= 1) {
        if (t < off) red[t] += red[t + off];
        __syncthreads();
    }
    if (t == 0) g_hn2[b] = red[0];
}

// ---------------------------------------------------------------- k_hc (HMMA)
// smem: A 128x512B (64KB), B 128x512B (64KB), bias 512B, srcs 512B, part 1KB
#define HC_A 0
#define HC_B 65536
#define HC_BIAS 131072
#define HC_SRC  131584
#define HC_PART 132096
#define SMEM_HC_BYTES (HC_PART + 1024)

__global__ __launch_bounds__(256, 1) void k_hc(const float* __restrict__ cx,
                                               const float* __restrict__ W,
                                               const float* __restrict__ be) {
    extern __shared__ char smem[];
    uint32_t sb = smem_to_u32(smem);
    float* bias_s = (float*)(smem + HC_BIAS);
    int*   srcs   = (int*)(smem + HC_SRC);
    float* part   = (float*)(smem + HC_PART);
    int tid = threadIdx.x, lane = tid & 31, wid = tid >> 5;
    int wr = wid & 3, wc = wid >> 2;
    int tile = blockIdx.x;

    if (tid < 128) {
        int p = tile * 128 + tid;
        srcs[tid]   = (p < M_TOT) ? g_src[p] : 0;
        bias_s[tid] = be[tid];
    }
    __syncthreads();

    // A: gathered cx rows fp32->fp16 (128 rows x 256 k), swizzled
#pragma unroll
    for (int i = 0; i < 16; i++) {
        int idx = tid + i * 256;           // 4096 x 16B
        int r = idx >> 5, kb = (idx & 31) * 16;
        const float4* s4 = (const float4*)(cx + (size_t)srcs[r] * D_INP + kb / 2);
        float4 v0 = s4[0], v1 = s4[1];
        __half2 h0 = __floats2half2_rn(v0.x, v0.y), h1 = __floats2half2_rn(v0.z, v0.w);
        __half2 h2 = __floats2half2_rn(v1.x, v1.y), h3 = __floats2half2_rn(v1.z, v1.w);
        *(uint4*)(smem + HC_A + r * 512 + (kb ^ ((r & 7) << 4))) =
            make_uint4(*(uint32_t*)&h0, *(uint32_t*)&h1, *(uint32_t*)&h2, *(uint32_t*)&h3);
    }
    // B: W rows fp32->fp16 (128 d x 256 k)
#pragma unroll
    for (int i = 0; i < 16; i++) {
        int idx = tid + i * 256;
        int r = idx >> 5, kb = (idx & 31) * 16;
        const float4* s4 = (const float4*)(W + (size_t)r * D_INP + kb / 2);
        float4 v0 = s4[0], v1 = s4[1];
        __half2 h0 = __floats2half2_rn(v0.x, v0.y), h1 = __floats2half2_rn(v0.z, v0.w);
        __half2 h2 = __floats2half2_rn(v1.x, v1.y), h3 = __floats2half2_rn(v1.z, v1.w);
        *(uint4*)(smem + HC_B + r * 512 + (kb ^ ((r & 7) << 4))) =
            make_uint4(*(uint32_t*)&h0, *(uint32_t*)&h1, *(uint32_t*)&h2, *(uint32_t*)&h3);
    }
    __syncthreads();

    float acc[2][8][4];
#pragma unroll
    for (int i = 0; i < 2; i++)
#pragma unroll
        for (int n = 0; n < 8; n++)
#pragma unroll
            for (int j = 0; j < 4; j++) acc[i][n][j] = 0.f;

#pragma unroll
    for (int ks = 0; ks < 16; ks++) {
        uint32_t a0[4], a1[4], bf[4][4];
        lda_frag(a0, sb + HC_A, wr * 32,      ks, lane, 512);
        lda_frag(a1, sb + HC_A, wr * 32 + 16, ks, lane, 512);
#pragma unroll
        for (int p = 0; p < 4; p++)
            ldb_frag(bf[p], sb + HC_B, wc * 64 + p * 16, ks, lane, 512);
#pragma unroll
        for (int nt = 0; nt < 8; nt++) {
            mma16816(acc[0][nt], a0, bf[nt >> 1][(nt & 1) * 2], bf[nt >> 1][(nt & 1) * 2 + 1]);
            mma16816(acc[1][nt], a1, bf[nt >> 1][(nt & 1) * 2], bf[nt >> 1][(nt & 1) * 2 + 1]);
        }
    }

    // epilogue: bias, fp16, write hc, norms
    float sumsq[2][2];
    sumsq[0][0] = sumsq[0][1] = sumsq[1][0] = sumsq[1][1] = 0.f;
#pragma unroll
    for (int mt2 = 0; mt2 < 2; mt2++)
#pragma unroll
        for (int hr = 0; hr < 2; hr++) {
            int row = wr * 32 + mt2 * 16 + (lane >> 2) + hr * 8;
            size_t gm = (size_t)tile * 128 + row;
#pragma unroll
            for (int nt = 0; nt < 8; nt++) {
                int d0 = wc * 64 + nt * 8 + (lane & 3) * 2;
                float v0 = acc[mt2][nt][hr * 2 + 0] + bias_s[d0];
                float v1 = acc[mt2][nt][hr * 2 + 1] + bias_s[d0 + 1];
                __half2 hp = __floats2half2_rn(v0, v1);
                float2 vr = __half22float2(hp);
                sumsq[mt2][hr] = fmaf(vr.x, vr.x, sumsq[mt2][hr]);
                sumsq[mt2][hr] = fmaf(vr.y, vr.y, sumsq[mt2][hr]);
                *(__half2*)(g_hc + gm * DIM + d0) = hp;
            }
        }
#pragma unroll
    for (int mt2 = 0; mt2 < 2; mt2++)
#pragma unroll
        for (int hr = 0; hr < 2; hr++) {
            float v = sumsq[mt2][hr];
            v += __shfl_xor_sync(0xFFFFFFFF, v, 1);
            v += __shfl_xor_sync(0xFFFFFFFF, v, 2);
            if ((lane & 3) == 0) {
                int row = wr * 32 + mt2 * 16 + (lane >> 2) + hr * 8;
                part[row * 2 + wc] = v;
            }
        }
    __syncthreads();
    if (tid < 128) {
        size_t gm = (size_t)tile * 128 + tid;
        g_hcn2[gm] = (gm < M_TOT) ? (part[tid * 2] + part[tid * 2 + 1]) : 3e38f;
    }
}

// ---------------------------------------------------------------- k_main (HMMA)
// smem: A 32KB, B 32KB, s_s [2][1024][10] 80KB
#define KM_A  0
#define KM_B  32768
#define KM_SS 65536
#define SMEM_MAIN_BYTES (KM_SS + 2 * B_ROWS * D_OUT * 4)

__global__ __launch_bounds__(256, 1) void k_main() {
    extern __shared__ char smem[];
    uint32_t sb = smem_to_u32(smem);
    float* s_s = (float*)(smem + KM_SS);
    int tid = threadIdx.x, lane = tid & 31, wid = tid >> 5;
    int wr = wid & 3, wc = wid >> 2;

    for (int i = tid; i < 2 * B_ROWS * D_OUT; i += 256) s_s[i] = 0.f;

    for (int mt = blockIdx.x; mt < N_MT; mt += gridDim.x) {
        __syncthreads();   // all prior epilogues done before B_s overwrite
        // load B tile (hc rows mt*128..+128, 256B/row)
#pragma unroll
        for (int i = 0; i < 8; i++) {
            int idx = tid + i * 256;          // 2048 x 16B
            int r = idx >> 4, kb = (idx & 15) * 16;
            *(uint4*)(smem + KM_B + r * 256 + (kb ^ ((r & 7) << 4))) =
                *(const uint4*)((const char*)g_hc + ((size_t)mt * 128 + r) * 256 + kb);
        }
        int mbase = mt * 128;
        float cn16[16];
#pragma unroll
        for (int nt = 0; nt < 8; nt++) {
            int m0 = mbase + wc * 64 + nt * 8 + (lane & 3) * 2;
            cn16[nt * 2]     = g_hcn2[m0];
            cn16[nt * 2 + 1] = g_hcn2[m0 + 1];
        }
        int c_lo = g_cls[mbase], c_hi = g_cls[mbase + 127];

        for (int chunk = 0; chunk < 8; chunk++) {
            if (chunk) __syncthreads();   // prior epilogue done (A_s safe)
            // load A chunk (h rows chunk*128..+128)
#pragma unroll
            for (int i = 0; i < 8; i++) {
                int idx = tid + i * 256;
                int r = idx >> 4, kb = (idx & 15) * 16;
                *(uint4*)(smem + KM_A + r * 256 + (kb ^ ((r & 7) << 4))) =
                    *(const uint4*)((const char*)g_h + ((size_t)chunk * 128 + r) * 256 + kb);
            }
            __syncthreads();

            float acc[2][8][4];
#pragma unroll
            for (int i = 0; i < 2; i++)
#pragma unroll
                for (int n = 0; n < 8; n++)
#pragma unroll
                    for (int j = 0; j < 4; j++) acc[i][n][j] = 0.f;

#pragma unroll
            for (int ks = 0; ks < 8; ks++) {
                uint32_t a0[4], a1[4], bf[4][4];
                lda_frag(a0, sb + KM_A, wr * 32,      ks, lane, 256);
                lda_frag(a1, sb + KM_A, wr * 32 + 16, ks, lane, 256);
#pragma unroll
                for (int p = 0; p < 4; p++)
                    ldb_frag(bf[p], sb + KM_B, wc * 64 + p * 16, ks, lane, 256);
#pragma unroll
                for (int nt = 0; nt < 8; nt++) {
                    mma16816(acc[0][nt], a0, bf[nt >> 1][(nt & 1) * 2], bf[nt >> 1][(nt & 1) * 2 + 1]);
                    mma16816(acc[1][nt], a1, bf[nt >> 1][(nt & 1) * 2], bf[nt >> 1][(nt & 1) * 2 + 1]);
                }
            }

            // epilogue: acc -> e
            int brow0 = chunk * 128 + wr * 32 + (lane >> 2);
            float hn[2][2];
#pragma unroll
            for (int mt2 = 0; mt2 < 2; mt2++)
#pragma unroll
                for (int hr = 0; hr < 2; hr++)
                    hn[mt2][hr] = g_hn2[brow0 + mt2 * 16 + hr * 8];
#pragma unroll
            for (int mt2 = 0; mt2 < 2; mt2++)
#pragma unroll
                for (int nt = 0; nt < 8; nt++)
#pragma unroll
                    for (int j2 = 0; j2 < 4; j2++) {
                        float sq = fmaf(-2.f, acc[mt2][nt][j2],
                                        hn[mt2][j2 >> 1] + cn16[nt * 2 + (j2 & 1)]);
                        sq = fmaxf(sq, 1e-30f);
                        float dist = sq * __frsqrt_rn(sq);
                        acc[mt2][nt][j2] = __expf(-dist);
                    }

            if (c_lo == c_hi) {
#pragma unroll
                for (int mt2 = 0; mt2 < 2; mt2++)
#pragma unroll
                    for (int hr = 0; hr < 2; hr++) {
                        float rs = 0.f;
#pragma unroll
                        for (int nt = 0; nt < 8; nt++)
                            rs += acc[mt2][nt][hr * 2] + acc[mt2][nt][hr * 2 + 1];
                        rs += __shfl_xor_sync(0xFFFFFFFF, rs, 1);
                        rs += __shfl_xor_sync(0xFFFFFFFF, rs, 2);
                        if ((lane & 3) == 0) {
                            int brow = brow0 + mt2 * 16 + hr * 8;
                            s_s[wc * (B_ROWS * D_OUT) + brow * D_OUT + c_lo] += rs;
                        }
                    }
            } else {
                int cls16[16];
#pragma unroll
                for (int nt = 0; nt < 8; nt++) {
                    int m0 = mbase + wc * 64 + nt * 8 + (lane & 3) * 2;
                    cls16[nt * 2]     = g_cls[m0];
                    cls16[nt * 2 + 1] = g_cls[m0 + 1];
                }
                for (int cc = c_lo; cc <= c_hi; cc++) {
#pragma unroll
                    for (int mt2 = 0; mt2 < 2; mt2++)
#pragma unroll
                        for (int hr = 0; hr < 2; hr++) {
                            float rs = 0.f;
#pragma unroll
                            for (int nt = 0; nt < 8; nt++) {
                                rs += (cls16[nt * 2]     == cc) ? acc[mt2][nt][hr * 2]     : 0.f;
                                rs += (cls16[nt * 2 + 1] == cc) ? acc[mt2][nt][hr * 2 + 1] : 0.f;
                            }
                            rs += __shfl_xor_sync(0xFFFFFFFF, rs, 1);
                            rs += __shfl_xor_sync(0xFFFFFFFF, rs, 2);
                            if ((lane & 3) == 0) {
                                int brow = brow0 + mt2 * 16 + hr * 8;
                                s_s[wc * (B_ROWS * D_OUT) + brow * D_OUT + cc] += rs;
                            }
                        }
                }
            }
        }
    }
    __syncthreads();
    for (int i = tid; i < B_ROWS * D_OUT; i += 256)
        g_part[(size_t)blockIdx.x * (B_ROWS * D_OUT) + i] =
            s_s[i] + s_s[B_ROWS * D_OUT + i];
}

// ---------------------------------------------------------------- k_final
__global__ void k_final(float* __restrict__ out, int nctas) {
    int b = blockIdx.x, t = threadIdx.x;   // 32 threads
    __shared__ float sc[D_OUT];
    if (t < D_OUT) {
        float s = 0.f;
        for (int p = 0; p < nctas; p++)
            s += g_part[(size_t)p * (B_ROWS * D_OUT) + b * D_OUT + t];
        sc[t] = s;
    }
    __syncthreads();
    if (t < D_OUT) {
        float tot = 0.f;
#pragma unroll
        for (int c = 0; c < D_OUT; c++) tot += sc[c];
        out[b * D_OUT + t] = logf(sc[t] / tot + 1e-7f);
    }
}

// ---------------------------------------------------------------- launch
extern "C" void kernel_launch(void* const* d_in, const int* in_sizes, int n_in,
                              void* d_out, int out_size) {
    const float* x  = (const float*)d_in[0];
    const float* cx = (const float*)d_in[2];
    const int*   cy = (const int*)d_in[3];
    const float* W  = (const float*)d_in[4];
    const float* be = (const float*)d_in[5];
    float* out = (float*)d_out;

    int dev = 0;
    cudaGetDevice(&dev);
    int nsm = 148;
    cudaDeviceGetAttribute(&nsm, cudaDevAttrMultiProcessorCount, dev);
    if (nsm < 1 || nsm > MAX_CTAS) nsm = 148;

    cudaFuncSetAttribute(k_hc,   cudaFuncAttributeMaxDynamicSharedMemorySize, SMEM_HC_BYTES);
    cudaFuncSetAttribute(k_main, cudaFuncAttributeMaxDynamicSharedMemorySize, SMEM_MAIN_BYTES);

    k_hist<<<NBLK, 256>>>(cy);
    k_scan<<<1, 32>>>();
    k_rank<<<NBLK, 256>>>(cy);
    k_h<<<B_ROWS, 128>>>(x, W, be);
    k_hc<<<N_MT, 256, SMEM_HC_BYTES>>>(cx, W, be);
    k_main<<<nsm, 256, SMEM_MAIN_BYTES>>>();
    k_final<<<B_ROWS, 32>>>(out, nsm);
}

// round 5
// speedup vs baseline: 8.8954x; 1.6045x over previous
#include <cuda_runtime.h>
#include <cuda_fp16.h>
#include <math.h>
#include <stdint.h>

#define B_ROWS 1024
#define M_TOT  200000
#define D_INP  256
#define DIM    128
#define D_OUT  10
#define M_PAD  200192            /* 1564*128 */
#define N_MT   1564              /* m-tiles of 128 */
#define NBLK   782               /* histogram blocks of 256 */
#define MAX_CTAS 512

// ---------------------------------------------------------------- helpers
__device__ __forceinline__ uint32_t smem_to_u32(const void* p) {
    uint32_t a;
    asm("{ .reg .u64 t; cvta.to.shared.u64 t, %1; cvt.u32.u64 %0, t; }"
        : "=r"(a) : "l"(p));
    return a;
}
__device__ __forceinline__ void ldsm4(uint32_t r[4], uint32_t addr) {
    asm volatile("ldmatrix.sync.aligned.m8n8.x4.shared.b16 {%0,%1,%2,%3}, [%4];"
                 : "=r"(r[0]), "=r"(r[1]), "=r"(r[2]), "=r"(r[3]) : "r"(addr));
}
__device__ __forceinline__ void mma16816(float c[4], const uint32_t a[4],
                                         const uint32_t b0, const uint32_t b1) {
    asm volatile("mma.sync.aligned.m16n8k16.row.col.f32.f16.f16.f32 "
                 "{%0,%1,%2,%3}, {%4,%5,%6,%7}, {%8,%9}, {%0,%1,%2,%3};"
                 : "+f"(c[0]), "+f"(c[1]), "+f"(c[2]), "+f"(c[3])
                 : "r"(a[0]), "r"(a[1]), "r"(a[2]), "r"(a[3]), "r"(b0), "r"(b1));
}
__device__ __forceinline__ float sqrt_approx(float x) {
    float r; asm("sqrt.approx.f32 %0, %1;" : "=f"(r) : "f"(x)); return r;
}
__device__ __forceinline__ void lda_frag(uint32_t a[4], uint32_t base, int R0,
                                         int ks, int lane, int rstride) {
    int row = R0 + (lane & 15);
    int kb  = ks * 32 + ((lane >> 4) << 4);
    ldsm4(a, base + row * rstride + (kb ^ ((row & 7) << 4)));
}
__device__ __forceinline__ void ldb_frag(uint32_t b[4], uint32_t base, int N0,
                                         int ks, int lane, int rstride) {
    int row = N0 + (lane & 7) + ((lane >> 4) << 3);
    int kb  = ks * 32 + ((lane >> 3) & 1) * 16;
    ldsm4(b, base + row * rstride + (kb ^ ((row & 7) << 4)));
}

// ---------------------------------------------------------------- scratch
__device__ __half g_h   [B_ROWS * DIM];
__device__ float  g_hn2 [B_ROWS];
__device__ __half g_hc  [(size_t)M_PAD * DIM];
__device__ float  g_hcn2[M_PAD];
__device__ int    g_src [M_PAD];
__device__ int    g_cls [M_PAD];
__device__ int    g_bh  [NBLK * D_OUT];
__device__ int    g_boff[NBLK * D_OUT];
__device__ int    g_coff[D_OUT];
__device__ float  g_part[(size_t)MAX_CTAS * B_ROWS * D_OUT];

// ---------------------------------------------------------------- sort
__global__ void k_hist(const int* __restrict__ cy) {
    __shared__ int cnt[D_OUT];
    int t = threadIdx.x, b = blockIdx.x;
    if (t < D_OUT) cnt[t] = 0;
    __syncthreads();
    int m = b * 256 + t;
    if (m < M_TOT) atomicAdd(&cnt[cy[m]], 1);
    __syncthreads();
    if (t < D_OUT) g_bh[b * D_OUT + t] = cnt[t];
}
__global__ void k_scan() {
    __shared__ int tot[D_OUT];
    int t = threadIdx.x;
    if (t < D_OUT) {
        int run = 0;
        for (int b = 0; b < NBLK; b++) {
            int v = g_bh[b * D_OUT + t];
            g_boff[b * D_OUT + t] = run;
            run += v;
        }
        tot[t] = run;
    }
    __syncthreads();
    if (t == 0) {
        int off = 0;
        for (int c = 0; c < D_OUT; c++) { g_coff[c] = off; off += tot[c]; }
        for (int p = M_TOT; p < M_PAD; p++) g_cls[p] = D_OUT - 1;
    }
}
__global__ void k_rank(const int* __restrict__ cy) {
    __shared__ int cls[256];
    int t = threadIdx.x, b = blockIdx.x;
    int m = b * 256 + t;
    int c = (m < M_TOT) ? cy[m] : -1;
    cls[t] = c;
    __syncthreads();
    if (m < M_TOT) {
        int r = 0;
        for (int j = 0; j < t; j++) r += (cls[j] == c);
        int pos = g_coff[c] + g_boff[b * D_OUT + c] + r;
        g_src[pos] = m;
        g_cls[pos] = c;
    }
}

// ---------------------------------------------------------------- k_hq (h via HMMA)
#define HC_A 0
#define HC_B 65536
#define HC_BIAS 131072
#define HC_SRC  131584
#define HC_PART 132096
#define SMEM_HC_BYTES (HC_PART + 1024)

__global__ __launch_bounds__(256, 1) void k_hq(const float* __restrict__ x,
                                               const float* __restrict__ W,
                                               const float* __restrict__ be) {
    extern __shared__ char smem[];
    uint32_t sb = smem_to_u32(smem);
    float* bias_s = (float*)(smem + HC_BIAS);
    float* part   = (float*)(smem + HC_PART);
    int tid = threadIdx.x, lane = tid & 31, wid = tid >> 5;
    int wr = wid & 3, wc = wid >> 2;
    int tile = blockIdx.x;                 // 8 tiles of 128 rows

    if (tid < 128) bias_s[tid] = be[tid];
    __syncthreads();

#pragma unroll
    for (int i = 0; i < 16; i++) {
        int idx = tid + i * 256;
        int r = idx >> 5, kb = (idx & 31) * 16;
        const float4* s4 = (const float4*)(x + (size_t)(tile * 128 + r) * D_INP + kb / 2);
        float4 v0 = s4[0], v1 = s4[1];
        __half2 h0 = __floats2half2_rn(v0.x, v0.y), h1 = __floats2half2_rn(v0.z, v0.w);
        __half2 h2 = __floats2half2_rn(v1.x, v1.y), h3 = __floats2half2_rn(v1.z, v1.w);
        *(uint4*)(smem + HC_A + r * 512 + (kb ^ ((r & 7) << 4))) =
            make_uint4(*(uint32_t*)&h0, *(uint32_t*)&h1, *(uint32_t*)&h2, *(uint32_t*)&h3);
    }
#pragma unroll
    for (int i = 0; i < 16; i++) {
        int idx = tid + i * 256;
        int r = idx >> 5, kb = (idx & 31) * 16;
        const float4* s4 = (const float4*)(W + (size_t)r * D_INP + kb / 2);
        float4 v0 = s4[0], v1 = s4[1];
        __half2 h0 = __floats2half2_rn(v0.x, v0.y), h1 = __floats2half2_rn(v0.z, v0.w);
        __half2 h2 = __floats2half2_rn(v1.x, v1.y), h3 = __floats2half2_rn(v1.z, v1.w);
        *(uint4*)(smem + HC_B + r * 512 + (kb ^ ((r & 7) << 4))) =
            make_uint4(*(uint32_t*)&h0, *(uint32_t*)&h1, *(uint32_t*)&h2, *(uint32_t*)&h3);
    }
    __syncthreads();

    float acc[2][8][4];
#pragma unroll
    for (int i = 0; i < 2; i++)
#pragma unroll
        for (int n = 0; n < 8; n++)
#pragma unroll
            for (int j = 0; j < 4; j++) acc[i][n][j] = 0.f;
#pragma unroll
    for (int ks = 0; ks < 16; ks++) {
        uint32_t a0[4], a1[4], bf[4][4];
        lda_frag(a0, sb + HC_A, wr * 32,      ks, lane, 512);
        lda_frag(a1, sb + HC_A, wr * 32 + 16, ks, lane, 512);
#pragma unroll
        for (int p = 0; p < 4; p++)
            ldb_frag(bf[p], sb + HC_B, wc * 64 + p * 16, ks, lane, 512);
#pragma unroll
        for (int nt = 0; nt < 8; nt++) {
            mma16816(acc[0][nt], a0, bf[nt >> 1][(nt & 1) * 2], bf[nt >> 1][(nt & 1) * 2 + 1]);
            mma16816(acc[1][nt], a1, bf[nt >> 1][(nt & 1) * 2], bf[nt >> 1][(nt & 1) * 2 + 1]);
        }
    }

    float sumsq[2][2];
    sumsq[0][0] = sumsq[0][1] = sumsq[1][0] = sumsq[1][1] = 0.f;
#pragma unroll
    for (int mt2 = 0; mt2 < 2; mt2++)
#pragma unroll
        for (int hr = 0; hr < 2; hr++) {
            int row = wr * 32 + mt2 * 16 + (lane >> 2) + hr * 8;
            size_t gm = (size_t)tile * 128 + row;
#pragma unroll
            for (int nt = 0; nt < 8; nt++) {
                int d0 = wc * 64 + nt * 8 + (lane & 3) * 2;
                float v0 = acc[mt2][nt][hr * 2 + 0] + bias_s[d0];
                float v1 = acc[mt2][nt][hr * 2 + 1] + bias_s[d0 + 1];
                __half2 hp = __floats2half2_rn(v0, v1);
                float2 vr = __half22float2(hp);
                sumsq[mt2][hr] = fmaf(vr.x, vr.x, sumsq[mt2][hr]);
                sumsq[mt2][hr] = fmaf(vr.y, vr.y, sumsq[mt2][hr]);
                *(__half2*)(g_h + gm * DIM + d0) = hp;
            }
        }
#pragma unroll
    for (int mt2 = 0; mt2 < 2; mt2++)
#pragma unroll
        for (int hr = 0; hr < 2; hr++) {
            float v = sumsq[mt2][hr];
            v += __shfl_xor_sync(0xFFFFFFFF, v, 1);
            v += __shfl_xor_sync(0xFFFFFFFF, v, 2);
            if ((lane & 3) == 0) {
                int row = wr * 32 + mt2 * 16 + (lane >> 2) + hr * 8;
                part[row * 2 + wc] = v;
            }
        }
    __syncthreads();
    if (tid < 128)
        g_hn2[tile * 128 + tid] = part[tid * 2] + part[tid * 2 + 1];
}

// ---------------------------------------------------------------- k_hc (HMMA)
__global__ __launch_bounds__(256, 1) void k_hc(const float* __restrict__ cx,
                                               const float* __restrict__ W,
                                               const float* __restrict__ be) {
    extern __shared__ char smem[];
    uint32_t sb = smem_to_u32(smem);
    float* bias_s = (float*)(smem + HC_BIAS);
    int*   srcs   = (int*)(smem + HC_SRC);
    float* part   = (float*)(smem + HC_PART);
    int tid = threadIdx.x, lane = tid & 31, wid = tid >> 5;
    int wr = wid & 3, wc = wid >> 2;
    int tile = blockIdx.x;

    if (tid < 128) {
        int p = tile * 128 + tid;
        srcs[tid]   = (p < M_TOT) ? g_src[p] : 0;
        bias_s[tid] = be[tid];
    }
    __syncthreads();

#pragma unroll
    for (int i = 0; i < 16; i++) {
        int idx = tid + i * 256;
        int r = idx >> 5, kb = (idx & 31) * 16;
        const float4* s4 = (const float4*)(cx + (size_t)srcs[r] * D_INP + kb / 2);
        float4 v0 = s4[0], v1 = s4[1];
        __half2 h0 = __floats2half2_rn(v0.x, v0.y), h1 = __floats2half2_rn(v0.z, v0.w);
        __half2 h2 = __floats2half2_rn(v1.x, v1.y), h3 = __floats2half2_rn(v1.z, v1.w);
        *(uint4*)(smem + HC_A + r * 512 + (kb ^ ((r & 7) << 4))) =
            make_uint4(*(uint32_t*)&h0, *(uint32_t*)&h1, *(uint32_t*)&h2, *(uint32_t*)&h3);
    }
#pragma unroll
    for (int i = 0; i < 16; i++) {
        int idx = tid + i * 256;
        int r = idx >> 5, kb = (idx & 31) * 16;
        const float4* s4 = (const float4*)(W + (size_t)r * D_INP + kb / 2);
        float4 v0 = s4[0], v1 = s4[1];
        __half2 h0 = __floats2half2_rn(v0.x, v0.y), h1 = __floats2half2_rn(v0.z, v0.w);
        __half2 h2 = __floats2half2_rn(v1.x, v1.y), h3 = __floats2half2_rn(v1.z, v1.w);
        *(uint4*)(smem + HC_B + r * 512 + (kb ^ ((r & 7) << 4))) =
            make_uint4(*(uint32_t*)&h0, *(uint32_t*)&h1, *(uint32_t*)&h2, *(uint32_t*)&h3);
    }
    __syncthreads();

    float acc[2][8][4];
#pragma unroll
    for (int i = 0; i < 2; i++)
#pragma unroll
        for (int n = 0; n < 8; n++)
#pragma unroll
            for (int j = 0; j < 4; j++) acc[i][n][j] = 0.f;
#pragma unroll
    for (int ks = 0; ks < 16; ks++) {
        uint32_t a0[4], a1[4], bf[4][4];
        lda_frag(a0, sb + HC_A, wr * 32,      ks, lane, 512);
        lda_frag(a1, sb + HC_A, wr * 32 + 16, ks, lane, 512);
#pragma unroll
        for (int p = 0; p < 4; p++)
            ldb_frag(bf[p], sb + HC_B, wc * 64 + p * 16, ks, lane, 512);
#pragma unroll
        for (int nt = 0; nt < 8; nt++) {
            mma16816(acc[0][nt], a0, bf[nt >> 1][(nt & 1) * 2], bf[nt >> 1][(nt & 1) * 2 + 1]);
            mma16816(acc[1][nt], a1, bf[nt >> 1][(nt & 1) * 2], bf[nt >> 1][(nt & 1) * 2 + 1]);
        }
    }

    float sumsq[2][2];
    sumsq[0][0] = sumsq[0][1] = sumsq[1][0] = sumsq[1][1] = 0.f;
#pragma unroll
    for (int mt2 = 0; mt2 < 2; mt2++)
#pragma unroll
        for (int hr = 0; hr < 2; hr++) {
            int row = wr * 32 + mt2 * 16 + (lane >> 2) + hr * 8;
            size_t gm = (size_t)tile * 128 + row;
#pragma unroll
            for (int nt = 0; nt < 8; nt++) {
                int d0 = wc * 64 + nt * 8 + (lane & 3) * 2;
                float v0 = acc[mt2][nt][hr * 2 + 0] + bias_s[d0];
                float v1 = acc[mt2][nt][hr * 2 + 1] + bias_s[d0 + 1];
                __half2 hp = __floats2half2_rn(v0, v1);
                float2 vr = __half22float2(hp);
                sumsq[mt2][hr] = fmaf(vr.x, vr.x, sumsq[mt2][hr]);
                sumsq[mt2][hr] = fmaf(vr.y, vr.y, sumsq[mt2][hr]);
                *(__half2*)(g_hc + gm * DIM + d0) = hp;
            }
        }
#pragma unroll
    for (int mt2 = 0; mt2 < 2; mt2++)
#pragma unroll
        for (int hr = 0; hr < 2; hr++) {
            float v = sumsq[mt2][hr];
            v += __shfl_xor_sync(0xFFFFFFFF, v, 1);
            v += __shfl_xor_sync(0xFFFFFFFF, v, 2);
            if ((lane & 3) == 0) {
                int row = wr * 32 + mt2 * 16 + (lane >> 2) + hr * 8;
                part[row * 2 + wc] = v;
            }
        }
    __syncthreads();
    if (tid < 128) {
        size_t gm = (size_t)tile * 128 + tid;
        g_hcn2[gm] = (gm < M_TOT) ? (part[tid * 2] + part[tid * 2 + 1]) : 3e38f;
    }
}

// ---------------------------------------------------------------- k_main
#define KM_A0 0
#define KM_A1 32768
#define KM_B  65536
#define KM_SS 98304
#define SMEM_MAIN_BYTES (KM_SS + 2 * B_ROWS * D_OUT * 4)

__device__ __forceinline__ void load_a_chunk(char* smem, int off, int chunk, int tid) {
#pragma unroll
    for (int i = 0; i < 8; i++) {
        int idx = tid + i * 256;
        int r = idx >> 4, kb = (idx & 15) * 16;
        *(uint4*)(smem + off + r * 256 + (kb ^ ((r & 7) << 4))) =
            *(const uint4*)((const char*)g_h + ((size_t)chunk * 128 + r) * 256 + kb);
    }
}

__device__ __forceinline__ void mma_chunk(float (&acc)[2][8][4], uint32_t abase,
                                          uint32_t bbase, int wr, int wc, int lane) {
#pragma unroll
    for (int i = 0; i < 2; i++)
#pragma unroll
        for (int n = 0; n < 8; n++)
#pragma unroll
            for (int j = 0; j < 4; j++) acc[i][n][j] = 0.f;
#pragma unroll
    for (int ks = 0; ks < 8; ks++) {
        uint32_t a0[4], a1[4], bf[4][4];
        lda_frag(a0, abase, wr * 32,      ks, lane, 256);
        lda_frag(a1, abase, wr * 32 + 16, ks, lane, 256);
#pragma unroll
        for (int p = 0; p < 4; p++)
            ldb_frag(bf[p], bbase, wc * 64 + p * 16, ks, lane, 256);
#pragma unroll
        for (int nt = 0; nt < 8; nt++) {
            mma16816(acc[0][nt], a0, bf[nt >> 1][(nt & 1) * 2], bf[nt >> 1][(nt & 1) * 2 + 1]);
            mma16816(acc[1][nt], a1, bf[nt >> 1][(nt & 1) * 2], bf[nt >> 1][(nt & 1) * 2 + 1]);
        }
    }
}

__device__ __forceinline__ void epi_reduce_store(float (&rs)[2][2], float* s_s,
                                                 int cprev, int cls,
                                                 int wr, int wc, int lane) {
#pragma unroll
    for (int mt2 = 0; mt2 < 2; mt2++)
#pragma unroll
        for (int hr = 0; hr < 2; hr++) {
            float v = rs[mt2][hr];
            v += __shfl_xor_sync(0xFFFFFFFF, v, 1);
            v += __shfl_xor_sync(0xFFFFFFFF, v, 2);
            if ((lane & 3) == 0) {
                int brow = cprev * 128 + wr * 32 + (lane >> 2) + mt2 * 16 + hr * 8;
                s_s[wc * (B_ROWS * D_OUT) + brow * D_OUT + cls] += v;
            }
        }
}

// MMA of chunk c interleaved with epilogue of chunk cprev=c-1 (pure-class tile)
__device__ __forceinline__ void mma_chunk_epi(float (&accN)[2][8][4],
                                              const float (&accP)[2][8][4],
                                              uint32_t abase, uint32_t bbase,
                                              const float (&cn16)[16], float* s_s,
                                              int cprev, int cls,
                                              int wr, int wc, int lane) {
    float hn[2][2];
    int r0 = cprev * 128 + wr * 32 + (lane >> 2);
    hn[0][0] = g_hn2[r0];      hn[0][1] = g_hn2[r0 + 8];
    hn[1][0] = g_hn2[r0 + 16]; hn[1][1] = g_hn2[r0 + 24];
    float rs[2][2] = {{0.f, 0.f}, {0.f, 0.f}};
#pragma unroll
    for (int i = 0; i < 2; i++)
#pragma unroll
        for (int n = 0; n < 8; n++)
#pragma unroll
            for (int j = 0; j < 4; j++) accN[i][n][j] = 0.f;
#pragma unroll
    for (int ks = 0; ks < 8; ks++) {
        uint32_t a0[4], a1[4], bf[4][4];
        lda_frag(a0, abase, wr * 32,      ks, lane, 256);
        lda_frag(a1, abase, wr * 32 + 16, ks, lane, 256);
#pragma unroll
        for (int p = 0; p < 4; p++)
            ldb_frag(bf[p], bbase, wc * 64 + p * 16, ks, lane, 256);
#pragma unroll
        for (int nt = 0; nt < 8; nt++) {
            mma16816(accN[0][nt], a0, bf[nt >> 1][(nt & 1) * 2], bf[nt >> 1][(nt & 1) * 2 + 1]);
            mma16816(accN[1][nt], a1, bf[nt >> 1][(nt & 1) * 2], bf[nt >> 1][(nt & 1) * 2 + 1]);
        }
        // epilogue slice nt=ks of previous chunk (fills MMA pipe latency)
#pragma unroll
        for (int mt2 = 0; mt2 < 2; mt2++)
#pragma unroll
            for (int j2 = 0; j2 < 4; j2++) {
                float sq = fmaf(-2.f, accP[mt2][ks][j2],
                                hn[mt2][j2 >> 1] + cn16[ks * 2 + (j2 & 1)]);
                sq = fmaxf(sq, 1e-30f);
                rs[mt2][j2 >> 1] += __expf(-sqrt_approx(sq));
            }
    }
    epi_reduce_store(rs, s_s, cprev, cls, wr, wc, lane);
}

__device__ __forceinline__ void epi_only(const float (&accP)[2][8][4],
                                         const float (&cn16)[16], float* s_s,
                                         int cprev, int cls,
                                         int wr, int wc, int lane) {
    float hn[2][2];
    int r0 = cprev * 128 + wr * 32 + (lane >> 2);
    hn[0][0] = g_hn2[r0];      hn[0][1] = g_hn2[r0 + 8];
    hn[1][0] = g_hn2[r0 + 16]; hn[1][1] = g_hn2[r0 + 24];
    float rs[2][2] = {{0.f, 0.f}, {0.f, 0.f}};
#pragma unroll
    for (int nt = 0; nt < 8; nt++)
#pragma unroll
        for (int mt2 = 0; mt2 < 2; mt2++)
#pragma unroll
            for (int j2 = 0; j2 < 4; j2++) {
                float sq = fmaf(-2.f, accP[mt2][nt][j2],
                                hn[mt2][j2 >> 1] + cn16[nt * 2 + (j2 & 1)]);
                sq = fmaxf(sq, 1e-30f);
                rs[mt2][j2 >> 1] += __expf(-sqrt_approx(sq));
            }
    epi_reduce_store(rs, s_s, cprev, cls, wr, wc, lane);
}

__global__ __launch_bounds__(256, 1) void k_main() {
    extern __shared__ char smem[];
    uint32_t sb = smem_to_u32(smem);
    float* s_s = (float*)(smem + KM_SS);
    int tid = threadIdx.x, lane = tid & 31, wid = tid >> 5;
    int wr = wid & 3, wc = wid >> 2;
    uint32_t A0 = sb + KM_A0, A1 = sb + KM_A1, BB = sb + KM_B;

    for (int i = tid; i < 2 * B_ROWS * D_OUT; i += 256) s_s[i] = 0.f;

    float acc0[2][8][4], acc1[2][8][4];

    for (int mt = blockIdx.x; mt < N_MT; mt += gridDim.x) {
        __syncthreads();   // prior mt fully done before B/A overwrite
        // B tile (hc rows mt*128..+128)
#pragma unroll
        for (int i = 0; i < 8; i++) {
            int idx = tid + i * 256;
            int r = idx >> 4, kb = (idx & 15) * 16;
            *(uint4*)(smem + KM_B + r * 256 + (kb ^ ((r & 7) << 4))) =
                *(const uint4*)((const char*)g_hc + ((size_t)mt * 128 + r) * 256 + kb);
        }
        load_a_chunk(smem, KM_A0, 0, tid);
        int mbase = mt * 128;
        float cn16[16];
#pragma unroll
        for (int nt = 0; nt < 8; nt++) {
            int m0 = mbase + wc * 64 + nt * 8 + (lane & 3) * 2;
            cn16[nt * 2]     = g_hcn2[m0];
            cn16[nt * 2 + 1] = g_hcn2[m0 + 1];
        }
        int c_lo = g_cls[mbase], c_hi = g_cls[mbase + 127];
        __syncthreads();

        if (c_lo == c_hi) {
            mma_chunk(acc0, A0, BB, wr, wc, lane);
#pragma unroll 1
            for (int cp = 0; cp < 3; cp++) {
                int c = cp * 2 + 1;
                load_a_chunk(smem, KM_A1, c, tid);
                __syncthreads();
                mma_chunk_epi(acc1, acc0, A1, BB, cn16, s_s, c - 1, c_lo, wr, wc, lane);
                load_a_chunk(smem, KM_A0, c + 1, tid);
                __syncthreads();
                mma_chunk_epi(acc0, acc1, A0, BB, cn16, s_s, c, c_lo, wr, wc, lane);
            }
            load_a_chunk(smem, KM_A1, 7, tid);
            __syncthreads();
            mma_chunk_epi(acc1, acc0, A1, BB, cn16, s_s, 6, c_lo, wr, wc, lane);
            epi_only(acc1, cn16, s_s, 7, c_lo, wr, wc, lane);
        } else {
            int cls16[16];
#pragma unroll
            for (int nt = 0; nt < 8; nt++) {
                int m0 = mbase + wc * 64 + nt * 8 + (lane & 3) * 2;
                cls16[nt * 2]     = g_cls[m0];
                cls16[nt * 2 + 1] = g_cls[m0 + 1];
            }
#pragma unroll 1
            for (int chunk = 0; chunk < 8; chunk++) {
                if (chunk) {
                    __syncthreads();
                    load_a_chunk(smem, KM_A0, chunk, tid);
                    __syncthreads();
                }
                mma_chunk(acc0, A0, BB, wr, wc, lane);
                int r0 = chunk * 128 + wr * 32 + (lane >> 2);
                float hn[2][2];
                hn[0][0] = g_hn2[r0];      hn[0][1] = g_hn2[r0 + 8];
                hn[1][0] = g_hn2[r0 + 16]; hn[1][1] = g_hn2[r0 + 24];
#pragma unroll
                for (int mt2 = 0; mt2 < 2; mt2++)
#pragma unroll
                    for (int nt = 0; nt < 8; nt++)
#pragma unroll
                        for (int j2 = 0; j2 < 4; j2++) {
                            float sq = fmaf(-2.f, acc0[mt2][nt][j2],
                                            hn[mt2][j2 >> 1] + cn16[nt * 2 + (j2 & 1)]);
                            sq = fmaxf(sq, 1e-30f);
                            acc0[mt2][nt][j2] = __expf(-sqrt_approx(sq));
                        }
                for (int cc = c_lo; cc <= c_hi; cc++) {
                    float rs[2][2] = {{0.f, 0.f}, {0.f, 0.f}};
#pragma unroll
                    for (int nt = 0; nt < 8; nt++)
#pragma unroll
                        for (int mt2 = 0; mt2 < 2; mt2++)
#pragma unroll
                            for (int j2 = 0; j2 < 4; j2++)
                                rs[mt2][j2 >> 1] +=
                                    (cls16[nt * 2 + (j2 & 1)] == cc) ? acc0[mt2][nt][j2] : 0.f;
                    epi_reduce_store(rs, s_s, chunk, cc, wr, wc, lane);
                }
            }
        }
    }
    __syncthreads();
    for (int i = tid; i < B_ROWS * D_OUT; i += 256)
        g_part[(size_t)blockIdx.x * (B_ROWS * D_OUT) + i] =
            s_s[i] + s_s[B_ROWS * D_OUT + i];
}

// ---------------------------------------------------------------- k_final
__global__ void k_final(float* __restrict__ out, int nctas) {
    __shared__ float red[320];
    int b = blockIdx.x, t = threadIdx.x;    // 320 threads
    int g = t / 10, c = t - g * 10;
    float s = 0.f;
    for (int p = g; p < nctas; p += 32)
        s += g_part[(size_t)p * (B_ROWS * D_OUT) + b * D_OUT + c];
    red[t] = s;
    __syncthreads();
    if (t < 160) red[t] += red[t + 160]; __syncthreads();
    if (t < 80)  red[t] += red[t + 80];  __syncthreads();
    if (t < 40)  red[t] += red[t + 40];  __syncthreads();
    if (t < 20)  red[t] += red[t + 20];  __syncthreads();
    if (t < 10)  red[t] += red[t + 10];
    __syncthreads();
    if (t < 10) {
        float tot = 0.f;
#pragma unroll
        for (int cc = 0; cc < 10; cc++) tot += red[cc];
        out[b * D_OUT + t] = logf(red[t] / tot + 1e-7f);
    }
}

// ---------------------------------------------------------------- launch
extern "C" void kernel_launch(void* const* d_in, const int* in_sizes, int n_in,
                              void* d_out, int out_size) {
    const float* x  = (const float*)d_in[0];
    const float* cx = (const float*)d_in[2];
    const int*   cy = (const int*)d_in[3];
    const float* W  = (const float*)d_in[4];
    const float* be = (const float*)d_in[5];
    float* out = (float*)d_out;

    int dev = 0;
    cudaGetDevice(&dev);
    int nsm = 148;
    cudaDeviceGetAttribute(&nsm, cudaDevAttrMultiProcessorCount, dev);
    if (nsm < 1 || nsm > MAX_CTAS) nsm = 148;

    cudaFuncSetAttribute(k_hq,   cudaFuncAttributeMaxDynamicSharedMemorySize, SMEM_HC_BYTES);
    cudaFuncSetAttribute(k_hc,   cudaFuncAttributeMaxDynamicSharedMemorySize, SMEM_HC_BYTES);
    cudaFuncSetAttribute(k_main, cudaFuncAttributeMaxDynamicSharedMemorySize, SMEM_MAIN_BYTES);

    k_hist<<<NBLK, 256>>>(cy);
    k_scan<<<1, 32>>>();
    k_rank<<<NBLK, 256>>>(cy);
    k_hq<<<8, 256, SMEM_HC_BYTES>>>(x, W, be);
    k_hc<<<N_MT, 256, SMEM_HC_BYTES>>>(cx, W, be);
    k_main<<<nsm, 256, SMEM_MAIN_BYTES>>>();
    k_final<<<B_ROWS, 320>>>(out, nsm);
}

// round 6
// speedup vs baseline: 9.3186x; 1.0476x over previous
#include <cuda_runtime.h>
#include <cuda_fp16.h>
#include <math.h>
#include <stdint.h>

#define B_ROWS 1024
#define M_TOT  200000
#define D_INP  256
#define DIM    128
#define D_OUT  10
#define M_PAD  200192            /* 1564*128 */
#define N_MT   1564              /* m-tiles of 128 */
#define NBLK   782               /* histogram blocks of 256 */
#define MAX_CTAS 512

// ---------------------------------------------------------------- helpers
__device__ __forceinline__ uint32_t smem_to_u32(const void* p) {
    uint32_t a;
    asm("{ .reg .u64 t; cvta.to.shared.u64 t, %1; cvt.u32.u64 %0, t; }"
        : "=r"(a) : "l"(p));
    return a;
}
__device__ __forceinline__ void ldsm4(uint32_t r[4], uint32_t addr) {
    asm volatile("ldmatrix.sync.aligned.m8n8.x4.shared.b16 {%0,%1,%2,%3}, [%4];"
                 : "=r"(r[0]), "=r"(r[1]), "=r"(r[2]), "=r"(r[3]) : "r"(addr));
}
__device__ __forceinline__ void mma16816(float c[4], const uint32_t a[4],
                                         const uint32_t b0, const uint32_t b1) {
    asm volatile("mma.sync.aligned.m16n8k16.row.col.f32.f16.f16.f32 "
                 "{%0,%1,%2,%3}, {%4,%5,%6,%7}, {%8,%9}, {%0,%1,%2,%3};"
                 : "+f"(c[0]), "+f"(c[1]), "+f"(c[2]), "+f"(c[3])
                 : "r"(a[0]), "r"(a[1]), "r"(a[2]), "r"(a[3]), "r"(b0), "r"(b1));
}
__device__ __forceinline__ float sqrt_approx(float x) {
    float r; asm("sqrt.approx.f32 %0, %1;" : "=f"(r) : "f"(x)); return r;
}
// A-fragment ldmatrix (16 rows x 16 k)
__device__ __forceinline__ void lda_frag(uint32_t a[4], uint32_t base, int R0,
                                         int ks, int lane, int rstride) {
    int row = R0 + (lane & 15);
    int kb  = ks * 32 + ((lane >> 4) << 4);
    ldsm4(a, base + row * rstride + (kb ^ ((row & 7) << 4)));
}
// B-fragment ldmatrix: two n-tiles of 8
__device__ __forceinline__ void ldb_frag(uint32_t b[4], uint32_t base, int N0,
                                         int ks, int lane, int rstride) {
    int row = N0 + (lane & 7) + ((lane >> 4) << 3);
    int kb  = ks * 32 + ((lane >> 3) & 1) * 16;
    ldsm4(b, base + row * rstride + (kb ^ ((row & 7) << 4)));
}

// ---------------------------------------------------------------- scratch
__device__ __half g_h   [B_ROWS * DIM];
__device__ float  g_hn2 [B_ROWS];
__device__ __half g_hc  [(size_t)M_PAD * DIM];
__device__ float  g_hcn2[M_PAD];
__device__ int    g_src [M_PAD];
__device__ int    g_cls [M_PAD];
__device__ int    g_bh  [NBLK * D_OUT];
__device__ int    g_boff[NBLK * D_OUT];
__device__ int    g_coff[D_OUT];
__device__ float  g_part[(size_t)MAX_CTAS * B_ROWS * D_OUT];

// ---------------------------------------------------------------- sort
__global__ void k_hist(const int* __restrict__ cy) {
    __shared__ int cnt[D_OUT];
    int t = threadIdx.x, b = blockIdx.x;
    if (t < D_OUT) cnt[t] = 0;
    __syncthreads();
    int m = b * 256 + t;
    if (m < M_TOT) atomicAdd(&cnt[cy[m]], 1);
    __syncthreads();
    if (t < D_OUT) g_bh[b * D_OUT + t] = cnt[t];
}
__global__ void k_scan() {
    __shared__ int tot[D_OUT];
    int t = threadIdx.x;
    if (t < D_OUT) {
        int run = 0;
        for (int b = 0; b < NBLK; b++) {
            int v = g_bh[b * D_OUT + t];
            g_boff[b * D_OUT + t] = run;
            run += v;
        }
        tot[t] = run;
    }
    __syncthreads();
    if (t == 0) {
        int off = 0;
        for (int c = 0; c < D_OUT; c++) { g_coff[c] = off; off += tot[c]; }
        for (int p = M_TOT; p < M_PAD; p++) g_cls[p] = D_OUT - 1;
    }
}
__global__ void k_rank(const int* __restrict__ cy) {
    __shared__ int cls[256];
    int t = threadIdx.x, b = blockIdx.x;
    int m = b * 256 + t;
    int c = (m < M_TOT) ? cy[m] : -1;
    cls[t] = c;
    __syncthreads();
    if (m < M_TOT) {
        int r = 0;
        for (int j = 0; j < t; j++) r += (cls[j] == c);
        int pos = g_coff[c] + g_boff[b * D_OUT + c] + r;
        g_src[pos] = m;
        g_cls[pos] = c;
    }
}

// ---------------------------------------------------------------- projection GEMMs
#define HC_A 0
#define HC_B 65536
#define HC_BIAS 131072
#define HC_SRC  131584
#define HC_PART 132096
#define SMEM_HC_BYTES (HC_PART + 1024)

// Shared body: project 128 rows (from row pointers in srcs or direct) through W.
// 512 threads, 16 warps: wr=wid&7 (16-row strip), wc=wid>>3 (64-col half).
template <bool GATHER>
__device__ __forceinline__ void proj_body(const float* __restrict__ src_mat,
                                          const float* __restrict__ W,
                                          __half* __restrict__ out_h,
                                          float* __restrict__ out_n2,
                                          int tile, bool pad_check) {
    extern __shared__ char smem[];
    uint32_t sb = smem_to_u32(smem);
    float* bias_s = (float*)(smem + HC_BIAS);
    int*   srcs   = (int*)(smem + HC_SRC);
    float* part   = (float*)(smem + HC_PART);
    int tid = threadIdx.x, lane = tid & 31, wid = tid >> 5;
    int wr = wid & 7, wc = wid >> 3;

    __syncthreads();   // srcs/bias ready (caller filled)

    // A: 128 rows x 256 k fp32->fp16 swizzled (4096 x 16B, 8 iters @512thr)
#pragma unroll
    for (int i = 0; i < 8; i++) {
        int idx = tid + i * 512;
        int r = idx >> 5, kb = (idx & 31) * 16;
        size_t srow = GATHER ? (size_t)srcs[r] : ((size_t)tile * 128 + r);
        const float4* s4 = (const float4*)(src_mat + srow * D_INP + kb / 2);
        float4 v0 = s4[0], v1 = s4[1];
        __half2 h0 = __floats2half2_rn(v0.x, v0.y), h1 = __floats2half2_rn(v0.z, v0.w);
        __half2 h2 = __floats2half2_rn(v1.x, v1.y), h3 = __floats2half2_rn(v1.z, v1.w);
        *(uint4*)(smem + HC_A + r * 512 + (kb ^ ((r & 7) << 4))) =
            make_uint4(*(uint32_t*)&h0, *(uint32_t*)&h1, *(uint32_t*)&h2, *(uint32_t*)&h3);
    }
    // B: W (128 d x 256 k)
#pragma unroll
    for (int i = 0; i < 8; i++) {
        int idx = tid + i * 512;
        int r = idx >> 5, kb = (idx & 31) * 16;
        const float4* s4 = (const float4*)(W + (size_t)r * D_INP + kb / 2);
        float4 v0 = s4[0], v1 = s4[1];
        __half2 h0 = __floats2half2_rn(v0.x, v0.y), h1 = __floats2half2_rn(v0.z, v0.w);
        __half2 h2 = __floats2half2_rn(v1.x, v1.y), h3 = __floats2half2_rn(v1.z, v1.w);
        *(uint4*)(smem + HC_B + r * 512 + (kb ^ ((r & 7) << 4))) =
            make_uint4(*(uint32_t*)&h0, *(uint32_t*)&h1, *(uint32_t*)&h2, *(uint32_t*)&h3);
    }
    __syncthreads();

    float acc[8][4];
#pragma unroll
    for (int n = 0; n < 8; n++)
#pragma unroll
        for (int j = 0; j < 4; j++) acc[n][j] = 0.f;
#pragma unroll
    for (int ks = 0; ks < 16; ks++) {
        uint32_t a[4], bf[4][4];
        lda_frag(a, sb + HC_A, wr * 16, ks, lane, 512);
#pragma unroll
        for (int p = 0; p < 4; p++)
            ldb_frag(bf[p], sb + HC_B, wc * 64 + p * 16, ks, lane, 512);
#pragma unroll
        for (int nt = 0; nt < 8; nt++)
            mma16816(acc[nt], a, bf[nt >> 1][(nt & 1) * 2], bf[nt >> 1][(nt & 1) * 2 + 1]);
    }

    float sumsq[2] = {0.f, 0.f};
#pragma unroll
    for (int hr = 0; hr < 2; hr++) {
        int row = wr * 16 + (lane >> 2) + hr * 8;
        size_t gm = (size_t)tile * 128 + row;
#pragma unroll
        for (int nt = 0; nt < 8; nt++) {
            int d0 = wc * 64 + nt * 8 + (lane & 3) * 2;
            float v0 = acc[nt][hr * 2 + 0] + bias_s[d0];
            float v1 = acc[nt][hr * 2 + 1] + bias_s[d0 + 1];
            __half2 hp = __floats2half2_rn(v0, v1);
            float2 vr = __half22float2(hp);
            sumsq[hr] = fmaf(vr.x, vr.x, sumsq[hr]);
            sumsq[hr] = fmaf(vr.y, vr.y, sumsq[hr]);
            *(__half2*)(out_h + gm * DIM + d0) = hp;
        }
    }
#pragma unroll
    for (int hr = 0; hr < 2; hr++) {
        float v = sumsq[hr];
        v += __shfl_xor_sync(0xFFFFFFFF, v, 1);
        v += __shfl_xor_sync(0xFFFFFFFF, v, 2);
        if ((lane & 3) == 0) {
            int row = wr * 16 + (lane >> 2) + hr * 8;
            part[row * 2 + wc] = v;
        }
    }
    __syncthreads();
    if (tid < 128) {
        size_t gm = (size_t)tile * 128 + tid;
        float v = part[tid * 2] + part[tid * 2 + 1];
        out_n2[gm] = (!pad_check || gm < M_TOT) ? v : 3e38f;
    }
}

__global__ __launch_bounds__(512, 1) void k_hq(const float* __restrict__ x,
                                               const float* __restrict__ W,
                                               const float* __restrict__ be) {
    extern __shared__ char smem[];
    float* bias_s = (float*)(smem + HC_BIAS);
    if (threadIdx.x < 128) bias_s[threadIdx.x] = be[threadIdx.x];
    proj_body<false>(x, W, g_h, g_hn2, blockIdx.x, false);
}

__global__ __launch_bounds__(512, 1) void k_hc(const float* __restrict__ cx,
                                               const float* __restrict__ W,
                                               const float* __restrict__ be) {
    extern __shared__ char smem[];
    float* bias_s = (float*)(smem + HC_BIAS);
    int*   srcs   = (int*)(smem + HC_SRC);
    int tid = threadIdx.x;
    if (tid < 128) {
        int p = blockIdx.x * 128 + tid;
        srcs[tid]   = (p < M_TOT) ? g_src[p] : 0;
        bias_s[tid] = be[tid];
    }
    proj_body<true>(cx, W, g_hc, g_hcn2, blockIdx.x, true);
}

// ---------------------------------------------------------------- k_main
// 512 threads / 16 warps: wr=wid&7 (16-row strip of 128 B-rows), wc=wid>>3
#define KM_A0 0
#define KM_A1 32768
#define KM_B  65536
#define KM_SS 98304
#define SMEM_MAIN_BYTES (KM_SS + 2 * B_ROWS * D_OUT * 4)

__device__ __forceinline__ void load_a_chunk(char* smem, int off, int chunk, int tid) {
#pragma unroll
    for (int i = 0; i < 4; i++) {
        int idx = tid + i * 512;
        int r = idx >> 4, kb = (idx & 15) * 16;
        *(uint4*)(smem + off + r * 256 + (kb ^ ((r & 7) << 4))) =
            *(const uint4*)((const char*)g_h + ((size_t)chunk * 128 + r) * 256 + kb);
    }
}

__device__ __forceinline__ void mma_chunk(float (&acc)[8][4], uint32_t abase,
                                          uint32_t bbase, int wr, int wc, int lane) {
#pragma unroll
    for (int n = 0; n < 8; n++)
#pragma unroll
        for (int j = 0; j < 4; j++) acc[n][j] = 0.f;
#pragma unroll
    for (int ks = 0; ks < 8; ks++) {
        uint32_t a[4], bf[4][4];
        lda_frag(a, abase, wr * 16, ks, lane, 256);
#pragma unroll
        for (int p = 0; p < 4; p++)
            ldb_frag(bf[p], bbase, wc * 64 + p * 16, ks, lane, 256);
#pragma unroll
        for (int nt = 0; nt < 8; nt++)
            mma16816(acc[nt], a, bf[nt >> 1][(nt & 1) * 2], bf[nt >> 1][(nt & 1) * 2 + 1]);
    }
}

__device__ __forceinline__ void epi_reduce_store(float (&rs)[2], float* s_s,
                                                 int cprev, int cls,
                                                 int wr, int wc, int lane) {
#pragma unroll
    for (int hr = 0; hr < 2; hr++) {
        float v = rs[hr];
        v += __shfl_xor_sync(0xFFFFFFFF, v, 1);
        v += __shfl_xor_sync(0xFFFFFFFF, v, 2);
        if ((lane & 3) == 0) {
            int brow = cprev * 128 + wr * 16 + (lane >> 2) + hr * 8;
            s_s[wc * (B_ROWS * D_OUT) + brow * D_OUT + cls] += v;
        }
    }
}

// MMA of chunk c interleaved with epilogue of chunk cprev=c-1 (pure-class tile)
__device__ __forceinline__ void mma_chunk_epi(float (&accN)[8][4],
                                              const float (&accP)[8][4],
                                              uint32_t abase, uint32_t bbase,
                                              const float (&cn16)[16], float* s_s,
                                              int cprev, int cls,
                                              int wr, int wc, int lane) {
    int r0 = cprev * 128 + wr * 16 + (lane >> 2);
    float hn0 = g_hn2[r0], hn1 = g_hn2[r0 + 8];
    float rs[2] = {0.f, 0.f};
#pragma unroll
    for (int n = 0; n < 8; n++)
#pragma unroll
        for (int j = 0; j < 4; j++) accN[n][j] = 0.f;
#pragma unroll
    for (int ks = 0; ks < 8; ks++) {
        uint32_t a[4], bf[4][4];
        lda_frag(a, abase, wr * 16, ks, lane, 256);
#pragma unroll
        for (int p = 0; p < 4; p++)
            ldb_frag(bf[p], bbase, wc * 64 + p * 16, ks, lane, 256);
#pragma unroll
        for (int nt = 0; nt < 8; nt++)
            mma16816(accN[nt], a, bf[nt >> 1][(nt & 1) * 2], bf[nt >> 1][(nt & 1) * 2 + 1]);
        // epilogue slice nt=ks of previous chunk (fills MMA pipe latency)
#pragma unroll
        for (int j2 = 0; j2 < 4; j2++) {
            float sq = fmaf(-2.f, accP[ks][j2],
                            ((j2 >> 1) ? hn1 : hn0) + cn16[ks * 2 + (j2 & 1)]);
            sq = fmaxf(sq, 1e-30f);
            rs[j2 >> 1] += __expf(-sqrt_approx(sq));
        }
    }
    epi_reduce_store(rs, s_s, cprev, cls, wr, wc, lane);
}

__device__ __forceinline__ void epi_only(const float (&accP)[8][4],
                                         const float (&cn16)[16], float* s_s,
                                         int cprev, int cls,
                                         int wr, int wc, int lane) {
    int r0 = cprev * 128 + wr * 16 + (lane >> 2);
    float hn0 = g_hn2[r0], hn1 = g_hn2[r0 + 8];
    float rs[2] = {0.f, 0.f};
#pragma unroll
    for (int nt = 0; nt < 8; nt++)
#pragma unroll
        for (int j2 = 0; j2 < 4; j2++) {
            float sq = fmaf(-2.f, accP[nt][j2],
                            ((j2 >> 1) ? hn1 : hn0) + cn16[nt * 2 + (j2 & 1)]);
            sq = fmaxf(sq, 1e-30f);
            rs[j2 >> 1] += __expf(-sqrt_approx(sq));
        }
    epi_reduce_store(rs, s_s, cprev, cls, wr, wc, lane);
}

__global__ __launch_bounds__(512, 1) void k_main() {
    extern __shared__ char smem[];
    uint32_t sb = smem_to_u32(smem);
    float* s_s = (float*)(smem + KM_SS);
    int tid = threadIdx.x, lane = tid & 31, wid = tid >> 5;
    int wr = wid & 7, wc = wid >> 3;
    uint32_t A0 = sb + KM_A0, A1 = sb + KM_A1, BB = sb + KM_B;

    for (int i = tid; i < 2 * B_ROWS * D_OUT; i += 512) s_s[i] = 0.f;

    float acc0[8][4], acc1[8][4];

    for (int mt = blockIdx.x; mt < N_MT; mt += gridDim.x) {
        __syncthreads();   // prior mt fully done before B/A overwrite
        // B tile (hc rows mt*128..+128): 2048 x 16B over 512 threads
#pragma unroll
        for (int i = 0; i < 4; i++) {
            int idx = tid + i * 512;
            int r = idx >> 4, kb = (idx & 15) * 16;
            *(uint4*)(smem + KM_B + r * 256 + (kb ^ ((r & 7) << 4))) =
                *(const uint4*)((const char*)g_hc + ((size_t)mt * 128 + r) * 256 + kb);
        }
        load_a_chunk(smem, KM_A0, 0, tid);
        int mbase = mt * 128;
        float cn16[16];
#pragma unroll
        for (int nt = 0; nt < 8; nt++) {
            int m0 = mbase + wc * 64 + nt * 8 + (lane & 3) * 2;
            cn16[nt * 2]     = g_hcn2[m0];
            cn16[nt * 2 + 1] = g_hcn2[m0 + 1];
        }
        int c_lo = g_cls[mbase], c_hi = g_cls[mbase + 127];
        __syncthreads();

        if (c_lo == c_hi) {
            mma_chunk(acc0, A0, BB, wr, wc, lane);
#pragma unroll 1
            for (int cp = 0; cp < 3; cp++) {
                int c = cp * 2 + 1;
                load_a_chunk(smem, KM_A1, c, tid);
                __syncthreads();
                mma_chunk_epi(acc1, acc0, A1, BB, cn16, s_s, c - 1, c_lo, wr, wc, lane);
                load_a_chunk(smem, KM_A0, c + 1, tid);
                __syncthreads();
                mma_chunk_epi(acc0, acc1, A0, BB, cn16, s_s, c, c_lo, wr, wc, lane);
            }
            load_a_chunk(smem, KM_A1, 7, tid);
            __syncthreads();
            mma_chunk_epi(acc1, acc0, A1, BB, cn16, s_s, 6, c_lo, wr, wc, lane);
            epi_only(acc1, cn16, s_s, 7, c_lo, wr, wc, lane);
        } else {
            int cls16[16];
#pragma unroll
            for (int nt = 0; nt < 8; nt++) {
                int m0 = mbase + wc * 64 + nt * 8 + (lane & 3) * 2;
                cls16[nt * 2]     = g_cls[m0];
                cls16[nt * 2 + 1] = g_cls[m0 + 1];
            }
#pragma unroll 1
            for (int chunk = 0; chunk < 8; chunk++) {
                if (chunk) {
                    __syncthreads();
                    load_a_chunk(smem, KM_A0, chunk, tid);
                    __syncthreads();
                }
                mma_chunk(acc0, A0, BB, wr, wc, lane);
                int r0 = chunk * 128 + wr * 16 + (lane >> 2);
                float hn0 = g_hn2[r0], hn1 = g_hn2[r0 + 8];
#pragma unroll
                for (int nt = 0; nt < 8; nt++)
#pragma unroll
                    for (int j2 = 0; j2 < 4; j2++) {
                        float sq = fmaf(-2.f, acc0[nt][j2],
                                        ((j2 >> 1) ? hn1 : hn0) + cn16[nt * 2 + (j2 & 1)]);
                        sq = fmaxf(sq, 1e-30f);
                        acc0[nt][j2] = __expf(-sqrt_approx(sq));
                    }
                for (int cc = c_lo; cc <= c_hi; cc++) {
                    float rs[2] = {0.f, 0.f};
#pragma unroll
                    for (int nt = 0; nt < 8; nt++)
#pragma unroll
                        for (int j2 = 0; j2 < 4; j2++)
                            rs[j2 >> 1] +=
                                (cls16[nt * 2 + (j2 & 1)] == cc) ? acc0[nt][j2] : 0.f;
                    epi_reduce_store(rs, s_s, chunk, cc, wr, wc, lane);
                }
            }
        }
    }
    __syncthreads();
    for (int i = tid; i < B_ROWS * D_OUT; i += 512)
        g_part[(size_t)blockIdx.x * (B_ROWS * D_OUT) + i] =
            s_s[i] + s_s[B_ROWS * D_OUT + i];
}

// ---------------------------------------------------------------- k_final
__global__ void k_final(float* __restrict__ out, int nctas) {
    __shared__ float red[320];
    int b = blockIdx.x, t = threadIdx.x;    // 320 threads
    int g = t / 10, c = t - g * 10;
    float s = 0.f;
    for (int p = g; p < nctas; p += 32)
        s += g_part[(size_t)p * (B_ROWS * D_OUT) + b * D_OUT + c];
    red[t] = s;
    __syncthreads();
    if (t < 160) red[t] += red[t + 160]; __syncthreads();
    if (t < 80)  red[t] += red[t + 80];  __syncthreads();
    if (t < 40)  red[t] += red[t + 40];  __syncthreads();
    if (t < 20)  red[t] += red[t + 20];  __syncthreads();
    if (t < 10)  red[t] += red[t + 10];
    __syncthreads();
    if (t < 10) {
        float tot = 0.f;
#pragma unroll
        for (int cc = 0; cc < 10; cc++) tot += red[cc];
        out[b * D_OUT + t] = logf(red[t] / tot + 1e-7f);
    }
}

// ---------------------------------------------------------------- launch
extern "C" void kernel_launch(void* const* d_in, const int* in_sizes, int n_in,
                              void* d_out, int out_size) {
    const float* x  = (const float*)d_in[0];
    const float* cx = (const float*)d_in[2];
    const int*   cy = (const int*)d_in[3];
    const float* W  = (const float*)d_in[4];
    const float* be = (const float*)d_in[5];
    float* out = (float*)d_out;

    int dev = 0;
    cudaGetDevice(&dev);
    int nsm = 148;
    cudaDeviceGetAttribute(&nsm, cudaDevAttrMultiProcessorCount, dev);
    if (nsm < 1 || nsm > MAX_CTAS) nsm = 148;

    cudaFuncSetAttribute(k_hq,   cudaFuncAttributeMaxDynamicSharedMemorySize, SMEM_HC_BYTES);
    cudaFuncSetAttribute(k_hc,   cudaFuncAttributeMaxDynamicSharedMemorySize, SMEM_HC_BYTES);
    cudaFuncSetAttribute(k_main, cudaFuncAttributeMaxDynamicSharedMemorySize, SMEM_MAIN_BYTES);

    k_hist<<<NBLK, 256>>>(cy);
    k_scan<<<1, 32>>>();
    k_rank<<<NBLK, 256>>>(cy);
    k_hq<<<8, 512, SMEM_HC_BYTES>>>(x, W, be);
    k_hc<<<N_MT, 512, SMEM_HC_BYTES>>>(cx, W, be);
    k_main<<<nsm, 512, SMEM_MAIN_BYTES>>>();
    k_final<<<B_ROWS, 320>>>(out, nsm);
}